// round 1
// baseline (speedup 1.0000x reference)
#include <cuda_runtime.h>

// Problem constants
constexpr int NB   = 8;      // batch
constexpr int CH   = 512;    // channels
constexpr int HW   = 4096;   // 64*64
constexpr int HW2  = 2048;   // hw/2
// conv out channels = 256, viewed as (512, 2048)

// Scratch: __device__ globals (allocation-free per harness rules)
__device__ float g_phi  [NB * CH * HW2];          // (b,256,4096) == (b,512,2048)
__device__ float g_theta[NB * CH * HW2];
__device__ float g_gbuf [NB * CH * HW2];
__device__ float g_S    [(size_t)NB * HW2 * HW2]; // (b, m, n) = scores[n,m]
__device__ float g_y2   [NB * CH * HW2];          // (b, c, m) == (b,256,4096)

// ---------------------------------------------------------------------------
// Generic tiled SGEMM: C[i,j] = sum_k A'[i,k] * B'[k,j]
//   TA=0: A is MxK row-major (lda = row stride).  TA=1: A is KxM row-major.
//   TB=0: B is KxN row-major.                     TB=1: B is NxK row-major.
// Tiles: 128x128x16, 256 threads, 8x8 per-thread microtile.
// All M%128==0, N%128==0, K%16==0 in this problem -> no bounds checks.
// EPI: C += r1 + r2 (residual add, same layout/stride as C).
// ---------------------------------------------------------------------------
template <int TA, int TB, bool EPI>
__global__ void __launch_bounds__(256) sgemm_kernel(
    const float* __restrict__ A, const float* __restrict__ Bm, float* __restrict__ Cm,
    int lda, int ldb, int ldc, int K,
    long long sA, long long sB, long long sC,
    const float* __restrict__ r1, const float* __restrict__ r2)
{
    __shared__ float As[16][132];
    __shared__ float Bs[16][132];

    const float* Ab = A  + (long long)blockIdx.z * sA;
    const float* Bb = Bm + (long long)blockIdx.z * sB;
    float*       Cb = Cm + (long long)blockIdx.z * sC;

    const int tid = threadIdx.x;
    const int m0 = blockIdx.y * 128;
    const int n0 = blockIdx.x * 128;
    const int tx = tid & 15;        // column group (8 cols)
    const int ty = tid >> 4;        // row group (8 rows)

    float acc[8][8] = {};

    for (int k0 = 0; k0 < K; k0 += 16) {
        // ---- load A tile -> As[k][m] ----
        if (TA == 0) {
            // A: MxK. Read 128 rows x 16 cols, store transposed.
            const int row = tid >> 2;            // 0..63
            const int col = (tid & 3) << 2;      // 0,4,8,12
            #pragma unroll
            for (int r = 0; r < 2; r++) {
                const float4 av = *(const float4*)(Ab + (long long)(m0 + row + r * 64) * lda + k0 + col);
                As[col + 0][row + r * 64] = av.x;
                As[col + 1][row + r * 64] = av.y;
                As[col + 2][row + r * 64] = av.z;
                As[col + 3][row + r * 64] = av.w;
            }
        } else {
            // A: KxM. Read 16 rows x 128 cols, store direct.
            const int kk = tid >> 5;             // 0..7
            const int mm = (tid & 31) << 2;      // 0..124
            #pragma unroll
            for (int r = 0; r < 2; r++) {
                *(float4*)&As[kk + r * 8][mm] =
                    *(const float4*)(Ab + (long long)(k0 + kk + r * 8) * lda + m0 + mm);
            }
        }
        // ---- load B tile -> Bs[k][n] ----
        if (TB == 0) {
            const int kk = tid >> 5;
            const int nn = (tid & 31) << 2;
            #pragma unroll
            for (int r = 0; r < 2; r++) {
                *(float4*)&Bs[kk + r * 8][nn] =
                    *(const float4*)(Bb + (long long)(k0 + kk + r * 8) * ldb + n0 + nn);
            }
        } else {
            // B: NxK. Read 128 rows x 16 cols, store transposed.
            const int row = tid >> 2;
            const int col = (tid & 3) << 2;
            #pragma unroll
            for (int r = 0; r < 2; r++) {
                const float4 bv = *(const float4*)(Bb + (long long)(n0 + row + r * 64) * ldb + k0 + col);
                Bs[col + 0][row + r * 64] = bv.x;
                Bs[col + 1][row + r * 64] = bv.y;
                Bs[col + 2][row + r * 64] = bv.z;
                Bs[col + 3][row + r * 64] = bv.w;
            }
        }
        __syncthreads();

        #pragma unroll
        for (int kk = 0; kk < 16; kk++) {
            float ra[8], rb[8];
            *(float4*)&ra[0] = *(const float4*)&As[kk][ty * 8];
            *(float4*)&ra[4] = *(const float4*)&As[kk][ty * 8 + 4];
            *(float4*)&rb[0] = *(const float4*)&Bs[kk][tx * 8];
            *(float4*)&rb[4] = *(const float4*)&Bs[kk][tx * 8 + 4];
            #pragma unroll
            for (int i = 0; i < 8; i++)
                #pragma unroll
                for (int j = 0; j < 8; j++)
                    acc[i][j] = fmaf(ra[i], rb[j], acc[i][j]);
        }
        __syncthreads();
    }

    // ---- epilogue / store ----
    #pragma unroll
    for (int i = 0; i < 8; i++) {
        const long long off = (long long)(m0 + ty * 8 + i) * ldc + n0 + tx * 8;
        #pragma unroll
        for (int j4 = 0; j4 < 2; j4++) {
            float4 o;
            o.x = acc[i][j4 * 4 + 0];
            o.y = acc[i][j4 * 4 + 1];
            o.z = acc[i][j4 * 4 + 2];
            o.w = acc[i][j4 * 4 + 3];
            if (EPI) {
                const long long roff = (long long)blockIdx.z * sC + off + j4 * 4;
                const float4 a1 = *(const float4*)(r1 + roff);
                const float4 a2 = *(const float4*)(r2 + roff);
                o.x += a1.x + a2.x;  o.y += a1.y + a2.y;
                o.z += a1.z + a2.z;  o.w += a1.w + a2.w;
            }
            *(float4*)(Cb + off + j4 * 4) = o;
        }
    }
}

// ---------------------------------------------------------------------------
// Row softmax over rows of length 2048 (S[m, :], softmax over n).
// One block of 256 threads per row; 8 elements/thread via 2x float4.
// ---------------------------------------------------------------------------
__global__ void __launch_bounds__(256) softmax_kernel(float* __restrict__ S)
{
    float* p = S + (size_t)blockIdx.x * HW2;
    const int tid = threadIdx.x;

    float4 v0 = ((const float4*)p)[tid];
    float4 v1 = ((const float4*)p)[tid + 256];

    float mx = fmaxf(fmaxf(fmaxf(v0.x, v0.y), fmaxf(v0.z, v0.w)),
                     fmaxf(fmaxf(v1.x, v1.y), fmaxf(v1.z, v1.w)));

    __shared__ float red[8];
    #pragma unroll
    for (int o = 16; o > 0; o >>= 1) mx = fmaxf(mx, __shfl_xor_sync(0xffffffffu, mx, o));
    if ((tid & 31) == 0) red[tid >> 5] = mx;
    __syncthreads();
    mx = red[0];
    #pragma unroll
    for (int i = 1; i < 8; i++) mx = fmaxf(mx, red[i]);
    __syncthreads();

    v0.x = __expf(v0.x - mx); v0.y = __expf(v0.y - mx);
    v0.z = __expf(v0.z - mx); v0.w = __expf(v0.w - mx);
    v1.x = __expf(v1.x - mx); v1.y = __expf(v1.y - mx);
    v1.z = __expf(v1.z - mx); v1.w = __expf(v1.w - mx);

    float sm = v0.x + v0.y + v0.z + v0.w + v1.x + v1.y + v1.z + v1.w;
    #pragma unroll
    for (int o = 16; o > 0; o >>= 1) sm += __shfl_xor_sync(0xffffffffu, sm, o);
    if ((tid & 31) == 0) red[tid >> 5] = sm;
    __syncthreads();
    sm = red[0];
    #pragma unroll
    for (int i = 1; i < 8; i++) sm += red[i];

    const float inv = 1.0f / sm;
    v0.x *= inv; v0.y *= inv; v0.z *= inv; v0.w *= inv;
    v1.x *= inv; v1.y *= inv; v1.z *= inv; v1.w *= inv;

    ((float4*)p)[tid]       = v0;
    ((float4*)p)[tid + 256] = v1;
}

// ---------------------------------------------------------------------------
extern "C" void kernel_launch(void* const* d_in, const int* in_sizes, int n_in,
                              void* d_out, int out_size)
{
    const float* q    = (const float*)d_in[0];
    const float* k    = (const float*)d_in[1];
    const float* v    = (const float*)d_in[2];
    const float* Wphi = (const float*)d_in[3];
    const float* Wth  = (const float*)d_in[4];
    const float* Wg   = (const float*)d_in[5];
    const float* Wm   = (const float*)d_in[6];
    float* out = (float*)d_out;

    float *phi, *theta, *gg, *S, *y2;
    cudaGetSymbolAddress((void**)&phi,   g_phi);
    cudaGetSymbolAddress((void**)&theta, g_theta);
    cudaGetSymbolAddress((void**)&gg,    g_gbuf);
    cudaGetSymbolAddress((void**)&S,     g_S);
    cudaGetSymbolAddress((void**)&y2,    g_y2);

    const dim3 blk(256);
    const long long sX  = (long long)CH * HW;      // 2097152: q/k/v/out batch stride
    const long long sP  = (long long)CH * HW2;     // 1048576: phi/theta/g/y2 batch stride
    const long long sS  = (long long)HW2 * HW2;    // 4194304: scores batch stride

    // 1) 1x1 convs: C(256x4096) = W(256x512) @ X(512x4096)       [NN]
    sgemm_kernel<0,0,false><<<dim3(32, 2, NB), blk>>>(Wphi, q, phi, CH, HW, HW, CH, 0, sX, sP, nullptr, nullptr);
    sgemm_kernel<0,0,false><<<dim3(32, 2, NB), blk>>>(Wth,  k, theta, CH, HW, HW, CH, 0, sX, sP, nullptr, nullptr);
    sgemm_kernel<0,0,false><<<dim3(32, 2, NB), blk>>>(Wg,   v, gg,    CH, HW, HW, CH, 0, sX, sP, nullptr, nullptr);

    // 2) scores: S[m,n] = sum_c phi[c,m] * theta[c,n]            [TN], K=512
    sgemm_kernel<1,0,false><<<dim3(16, 16, NB), blk>>>(phi, theta, S, HW2, HW2, HW2, CH, sP, sP, sS, nullptr, nullptr);

    // 3) softmax over n (rows of S), 8*2048 rows
    softmax_kernel<<<NB * HW2, blk>>>(S);

    // 4) y2[c,m] = sum_n g[c,n] * S'[m,n]                        [NT], K=2048
    sgemm_kernel<0,1,false><<<dim3(16, 4, NB), blk>>>(gg, S, y2, HW2, HW2, HW2, HW2, sP, sS, sP, nullptr, nullptr);

    // 5) out = W_mask(512x256) @ y3(256x4096) + q + v            [NN + residual], K=256
    sgemm_kernel<0,0,true><<<dim3(32, 4, NB), blk>>>(Wm, y2, out, 256, HW, HW, 256, 0, sP, sX, q, v);
}